// round 14
// baseline (speedup 1.0000x reference)
#include <cuda_runtime.h>

// FINAL — terminal kernel, validated nine consecutive rounds with identical
// source (R4/R6-R13: ncu 3.648, 3.648, 3.584, 3.584, 4.256, 3.936, 3.712,
// 3.840, 3.648us; dur 4.608, 4.576, 4.544, 4.576, 6.880, 6.880, 4.576,
// 4.576, 4.576us; rel_err 0.0 in all thirteen rounds). dur_us is bimodal
// (~4.57 vs ~6.88us) from harness/replay state, not source; the
// identical-source spread exceeds every inter-variant delta ever measured.
//
// Output layout (66 floats): trace[64] then gates[2].
//
// Dead-code analysis of the reference: the color-refinement trace is
// independent of x, weights, and edge placement — col evolves all-0 ->
// all-1 -> all-2, mask is always all-true, and sig_mean[new_c] = E/N exactly
// each layer. Hence trace[1] = E/(4N), trace[2] = E/(2N), rest 0.
// gates = sigmoid(alpha_i). The GIN MLP stack is dead code with respect to
// the returned values.
//
// The kernel is at the single-launch structural floor: 2 LDG + 17 STG +
// 2 MUFU (~0.3us of work, the information-theoretic minimum: both alphas
// are runtime device inputs, 264 output bytes must be stored) inside a
// ~3.6-4.3us launch/drain envelope (T_ovh ~ 5000 cycles, DVFS-dependent).
// All ncu utilization rows ~0% — the binding constraint is the launch
// itself, not any pipe.
//
// Structure: fully parallel single warp. Lanes 0/1 issue the alpha LDGs in
// the first slots; lanes 0..15 concurrently do the 16x STG.128 zero/const
// fill (no register dependency on the loads); lanes 0/1 finish with their
// own sigmoid + STG.32 gate stores.

__global__ void __launch_bounds__(32, 1)
bfs_refine_out_kernel(const float* __restrict__ alpha0,
                      const float* __restrict__ alpha1,
                      float t1, float t2,
                      float* __restrict__ out)
{
    const int i = threadIdx.x;

    // Lanes 0/1: issue alpha loads in the first issue slots.
    float a = 0.0f;
    if (i == 0) a = __ldg(alpha0);
    if (i == 1) a = __ldg(alpha1);

    // Lanes 0..15: 16x STG.128 zero-fill of trace[0..63], independent of the
    // loads above, so they issue while the LDGs are in flight.
    if (i < 16) {
        float4 v = make_float4(0.0f, 0.0f, 0.0f, 0.0f);
        if (i == 0) { v.y = t1; v.z = t2; }
        reinterpret_cast<float4*>(out)[i] = v;
    }

    // Lanes 0/1: gate stores, each lane its own sigmoid + STG.32.
    if (i < 2) {
        out[64 + i] = 1.0f / (1.0f + __expf(-a));
    }
}

extern "C" void kernel_launch(void* const* d_in, const int* in_sizes, int n_in,
                              void* d_out, int out_size)
{
    // Input order: x, edge_index, W1_0, b1_0, W2_0, b2_0, alpha_0,
    //              W1_1, b1_1, W2_1, b2_1, alpha_1
    const float* alpha0 = (const float*)d_in[6];
    const float* alpha1 = (const float*)d_in[11];

    const long long n_nodes = (long long)in_sizes[0] / 127;  // x is [N, 127]
    const long long n_edges = (long long)in_sizes[1] / 2;    // edge_index is [2, E]

    const double ratio = (double)n_edges / (double)n_nodes;  // E/N
    const float t1 = (float)(ratio * 0.25);  // trace[1] = E/(4N)
    const float t2 = (float)(ratio * 0.5);   // trace[2] = E/(2N)

    bfs_refine_out_kernel<<<1, 32>>>(alpha0, alpha1, t1, t2, (float*)d_out);
}

// round 15
// speedup vs baseline: 1.1972x; 1.1972x over previous
#include <cuda_runtime.h>

// FINAL — terminal kernel, validated ten consecutive rounds with identical
// source (R4/R6-R14: ncu 3.648, 3.648, 3.584, 3.584, 4.256, 3.936, 3.712,
// 3.840, 3.648, 4.096us; dur 4.608, 4.576, 4.544, 4.576, 6.880, 6.880,
// 4.576, 4.576, 4.576, 5.440us; rel_err 0.0 in all fourteen rounds).
// dur_us variance (~4.55-6.9us) is harness/replay state, not source; the
// identical-source spread exceeds every inter-variant delta ever measured.
//
// Output layout (66 floats): trace[64] then gates[2].
//
// Dead-code analysis of the reference: the color-refinement trace is
// independent of x, weights, and edge placement — col evolves all-0 ->
// all-1 -> all-2, mask is always all-true, and sig_mean[new_c] = E/N exactly
// each layer. Hence trace[1] = E/(4N), trace[2] = E/(2N), rest 0.
// gates = sigmoid(alpha_i). The GIN MLP stack is dead code with respect to
// the returned values.
//
// The kernel is at the single-launch structural floor: 2 LDG + 17 STG +
// 2 MUFU (~0.3us of work, the information-theoretic minimum: both alphas
// are runtime device inputs, 264 output bytes must be stored) inside a
// ~3.6-4.3us launch/drain envelope (T_ovh ~ 5000 cycles, DVFS-dependent).
// All ncu utilization rows ~0% — the binding constraint is the launch
// itself, not any pipe.
//
// Structure: fully parallel single warp. Lanes 0/1 issue the alpha LDGs in
// the first slots; lanes 0..15 concurrently do the 16x STG.128 zero/const
// fill (no register dependency on the loads); lanes 0/1 finish with their
// own sigmoid + STG.32 gate stores.

__global__ void __launch_bounds__(32, 1)
bfs_refine_out_kernel(const float* __restrict__ alpha0,
                      const float* __restrict__ alpha1,
                      float t1, float t2,
                      float* __restrict__ out)
{
    const int i = threadIdx.x;

    // Lanes 0/1: issue alpha loads in the first issue slots.
    float a = 0.0f;
    if (i == 0) a = __ldg(alpha0);
    if (i == 1) a = __ldg(alpha1);

    // Lanes 0..15: 16x STG.128 zero-fill of trace[0..63], independent of the
    // loads above, so they issue while the LDGs are in flight.
    if (i < 16) {
        float4 v = make_float4(0.0f, 0.0f, 0.0f, 0.0f);
        if (i == 0) { v.y = t1; v.z = t2; }
        reinterpret_cast<float4*>(out)[i] = v;
    }

    // Lanes 0/1: gate stores, each lane its own sigmoid + STG.32.
    if (i < 2) {
        out[64 + i] = 1.0f / (1.0f + __expf(-a));
    }
}

extern "C" void kernel_launch(void* const* d_in, const int* in_sizes, int n_in,
                              void* d_out, int out_size)
{
    // Input order: x, edge_index, W1_0, b1_0, W2_0, b2_0, alpha_0,
    //              W1_1, b1_1, W2_1, b2_1, alpha_1
    const float* alpha0 = (const float*)d_in[6];
    const float* alpha1 = (const float*)d_in[11];

    const long long n_nodes = (long long)in_sizes[0] / 127;  // x is [N, 127]
    const long long n_edges = (long long)in_sizes[1] / 2;    // edge_index is [2, E]

    const double ratio = (double)n_edges / (double)n_nodes;  // E/N
    const float t1 = (float)(ratio * 0.25);  // trace[1] = E/(4N)
    const float t2 = (float)(ratio * 0.5);   // trace[2] = E/(2N)

    bfs_refine_out_kernel<<<1, 32>>>(alpha0, alpha1, t1, t2, (float*)d_out);
}